// round 15
// baseline (speedup 1.0000x reference)
#include <cuda_runtime.h>
#include <math.h>
#include <cstdint>

#define Bn 4
#define Sn 2048
#define Dn 1024
#define Hn 16
#define DHn 64
#define KDIM 1024

// ---------------- scratch (__device__ globals; no allocs allowed) ----------
__device__ float g_q[(size_t)Bn * Hn * Sn * DHn];     // Q [B,H,S,dh] scaled+tf32
__device__ float g_attn[(size_t)Bn * Sn * Dn];        // attn out [B,S,D] tf32+packed
__device__ float g_x[(size_t)Bn * Sn * Dn];           // x tf32+packed
__device__ float g_kfall[(size_t)Bn * Hn * Sn * DHn];
__device__ float g_vfall[(size_t)Bn * Hn * Sn * DHn];
__device__ float g_ka[(size_t)Bn * Hn * Sn * DHn];    // K tf32, dh-cols packed
__device__ float g_vt[(size_t)Bn * Hn * Sn * DHn];    // V^T [B,H,dh,S] tf32, packed
__device__ float g_wt1[(size_t)3072 * 1024];          // W_in^T  tf32+packed
__device__ float g_wt2[(size_t)1024 * 1024];          // W_out^T tf32+packed

__device__ __forceinline__ float to_tf32(float x) {
  float y;
  asm("cvt.rna.tf32.f32 %0, %1;" : "=f"(y) : "f"(x));
  return y;
}

__device__ __forceinline__ void mma1688(float* c, const uint32_t* a,
                                        const uint32_t* b) {
  asm volatile(
      "mma.sync.aligned.m16n8k8.row.col.f32.tf32.tf32.f32 "
      "{%0,%1,%2,%3}, {%4,%5,%6,%7}, {%8,%9}, {%0,%1,%2,%3};"
      : "+f"(c[0]), "+f"(c[1]), "+f"(c[2]), "+f"(c[3])
      : "r"(a[0]), "r"(a[1]), "r"(a[2]), "r"(a[3]), "r"(b[0]), "r"(b[1]));
}

__device__ __forceinline__ uint32_t smem_u32(const void* p) {
  uint32_t a;
  asm("{ .reg .u64 t; cvta.to.shared.u64 t, %1; cvt.u32.u64 %0, t; }"
      : "=r"(a) : "l"(p));
  return a;
}

__device__ __forceinline__ void cpasync16(uint32_t dst, const void* src) {
  asm volatile("cp.async.cg.shared.global [%0], [%1], 16;" ::"r"(dst),
               "l"(src) : "memory");
}

// ---------------------------------------------------------------------------
// device helpers for batched prep
// ---------------------------------------------------------------------------
__device__ __forceinline__ void wtrans_tile(const float* __restrict__ W,
                                            float* __restrict__ WT, int K,
                                            int N, int n0, int k0,
                                            float (*t)[33]) {
  const int tx = threadIdx.x & 31, ty = threadIdx.x >> 5;
#pragma unroll
  for (int i = 0; i < 4; ++i)
    t[ty + i * 8][tx] = W[(size_t)(k0 + ty + i * 8) * N + n0 + tx];
  __syncthreads();
  const int kp = (tx & ~7) | (2 * (tx & 3) + ((tx >> 2) & 1));
#pragma unroll
  for (int i = 0; i < 4; ++i)
    WT[(size_t)(n0 + ty + i * 8) * K + k0 + kp] = to_tf32(t[tx][ty + i * 8]);
}

__device__ __forceinline__ void packrow_quad(const float* __restrict__ S,
                                             float* __restrict__ D,
                                             size_t blk) {
  const size_t i = (blk * 256 + threadIdx.x) * 4;
  float4 v = *(const float4*)(S + i);
  const int off = (i & 4) ? 1 : 0;
  float* dst = D + (i & ~(size_t)7) + off;
  dst[0] = to_tf32(v.x);
  dst[2] = to_tf32(v.y);
  dst[4] = to_tf32(v.z);
  dst[6] = to_tf32(v.w);
}

// prep_pre: blocks [0,8192) pack x; [8192,11264) wtrans W_in; [11264,12288) W_out
__global__ __launch_bounds__(256) void prep_pre(
    const float* __restrict__ x, float* __restrict__ gx,
    const float* __restrict__ w_in, float* __restrict__ wt1,
    const float* __restrict__ w_out, float* __restrict__ wt2) {
  __shared__ float t[32][33];
  const int b = blockIdx.x;
  if (b < 8192) {
    packrow_quad(x, gx, (size_t)b);
  } else if (b < 11264) {
    const int idx = b - 8192;
    wtrans_tile(w_in, wt1, 1024, 3072, (idx % 96) * 32, (idx / 96) * 32, t);
  } else {
    const int idx = b - 11264;
    wtrans_tile(w_out, wt2, 1024, 1024, (idx % 32) * 32, (idx / 32) * 32, t);
  }
}

// prep_post: blocks [0,8192) pack K; [8192,16384) transpose+pack V
__global__ __launch_bounds__(256) void prep_post(
    const float* __restrict__ K, float* __restrict__ Ka,
    const float* __restrict__ V, float* __restrict__ VT) {
  __shared__ float t[32][33];
  const int b = blockIdx.x;
  if (b < 8192) {
    packrow_quad(K, Ka, (size_t)b);
  } else {
    const int idx = b - 8192;
    const int s0 = (idx & 63) * 32, d0 = ((idx >> 6) & 1) * 32, bh = idx >> 7;
    const float* Vb = V + (size_t)bh * Sn * DHn;
    float* Tb = VT + (size_t)bh * Sn * DHn;
    const int tx = threadIdx.x & 31, ty = threadIdx.x >> 5;
#pragma unroll
    for (int i = 0; i < 4; ++i)
      t[ty + i * 8][tx] =
          to_tf32(Vb[(size_t)(s0 + ty + i * 8) * DHn + d0 + tx]);
    __syncthreads();
    const int sx = (tx & ~7) | (2 * (tx & 3) + ((tx >> 2) & 1));
#pragma unroll
    for (int i = 0; i < 4; ++i)
      Tb[(size_t)(d0 + ty + i * 8) * Sn + s0 + sx] = t[tx][ty + i * 8];
  }
}

// ---------------------------------------------------------------------------
// tf32 HMMA GEMM (validated R12). 4 warps, CTA 128x128, warp 64x64, KC=32,
// 3-stage cp.async, 8-float-group XOR swizzle (conflict-free float2 loads).
// ---------------------------------------------------------------------------
#define KC 32
#define TILE_F (128 * 32)
#define STAGE_F (2 * TILE_F)
#define NSTAGE 3
#define GEMM_SMEM (NSTAGE * STAGE_F * 4)  // 98304 B

template <int MODE>
__global__ __launch_bounds__(128) void gemm_mma(
    const float* __restrict__ A, const float* __restrict__ Bt,
    const float* __restrict__ bias, float* __restrict__ C0,
    float* __restrict__ Ck, float* __restrict__ Cv) {
  extern __shared__ __align__(16) float sm[];
  const uint32_t sbase = smem_u32(sm);
  const int tid = threadIdx.x;
  const int m0 = blockIdx.y * 128, n0 = blockIdx.x * 128;
  const int warp = tid >> 5, lane = tid & 31;
  const int g = lane >> 2, c = lane & 3;
  const int wm = (warp & 1) * 64, wn = (warp >> 1) * 64;

  const float* Ab = A + (size_t)m0 * KDIM;
  const float* Bb = Bt + (size_t)n0 * KDIM;

  float acc[4][8][4];
#pragma unroll
  for (int mt = 0; mt < 4; ++mt)
#pragma unroll
    for (int nt = 0; nt < 8; ++nt)
#pragma unroll
      for (int r = 0; r < 4; ++r) acc[mt][nt][r] = 0.0f;

  const int NCH = KDIM / KC;

  auto issue = [&](int ch, int st) {
    const uint32_t As = sbase + (uint32_t)(st * STAGE_F) * 4;
    const uint32_t Bs = As + (uint32_t)TILE_F * 4;
    const int ko = ch * KC;
#pragma unroll
    for (int i = 0; i < 8; ++i) {
      const int idx = i * 128 + tid;
      const int r = idx >> 3, qi = idx & 7;
      const int gi = qi >> 1;
      const uint32_t dcol =
          (uint32_t)((((gi ^ (r & 3)) << 3) + ((qi & 1) << 2)));
      cpasync16(As + (uint32_t)(r * 32 + dcol) * 4,
                Ab + (size_t)r * KDIM + ko + qi * 4);
      cpasync16(Bs + (uint32_t)(r * 32 + dcol) * 4,
                Bb + (size_t)r * KDIM + ko + qi * 4);
    }
    asm volatile("cp.async.commit_group;" ::: "memory");
  };

  issue(0, 0);
  issue(1, 1);

  for (int ch = 0; ch < NCH; ++ch) {
    const int st = ch % NSTAGE;
    if (ch + 1 < NCH)
      asm volatile("cp.async.wait_group 1;" ::: "memory");
    else
      asm volatile("cp.async.wait_group 0;" ::: "memory");
    __syncthreads();
    if (ch + 2 < NCH) issue(ch + 2, (ch + 2) % NSTAGE);

    const uint32_t* Au = (const uint32_t*)(sm + st * STAGE_F);
    const uint32_t* Bu = Au + TILE_F;
#pragma unroll
    for (int ks = 0; ks < KC / 8; ++ks) {
      const int fcol = (((ks ^ (g & 3)) << 3) + 2 * c);
      uint32_t af[4][4], bf[8][2];
#pragma unroll
      for (int mt = 0; mt < 4; ++mt) {
        const int row = wm + mt * 16 + g;
        const uint2 lo = *(const uint2*)&Au[(row << 5) + fcol];
        const uint2 hi = *(const uint2*)&Au[((row + 8) << 5) + fcol];
        af[mt][0] = lo.x; af[mt][1] = hi.x;
        af[mt][2] = lo.y; af[mt][3] = hi.y;
      }
#pragma unroll
      for (int nt = 0; nt < 8; ++nt) {
        const uint2 b2 = *(const uint2*)&Bu[((wn + nt * 8 + g) << 5) + fcol];
        bf[nt][0] = b2.x; bf[nt][1] = b2.y;
      }
#pragma unroll
      for (int mt = 0; mt < 4; ++mt)
#pragma unroll
        for (int nt = 0; nt < 8; ++nt) mma1688(acc[mt][nt], af[mt], bf[nt]);
    }
  }

#pragma unroll
  for (int mt = 0; mt < 4; ++mt) {
#pragma unroll
    for (int nt = 0; nt < 8; ++nt) {
      const int row = m0 + wm + mt * 16 + g;
      const int col = n0 + wn + nt * 8 + 2 * c;
      const float b0 = bias[col], b1 = bias[col + 1];
      float2 v0 = {acc[mt][nt][0] + b0, acc[mt][nt][1] + b1};
      float2 v1 = {acc[mt][nt][2] + b0, acc[mt][nt][3] + b1};
      if (MODE == 0) {
        const int which = col >> 10, hd = col & 1023;
        float* Cp = (which == 0) ? C0 : ((which == 1) ? Ck : Cv);
        if (which == 0) {
          v0.x = to_tf32(v0.x * 0.125f); v0.y = to_tf32(v0.y * 0.125f);
          v1.x = to_tf32(v1.x * 0.125f); v1.y = to_tf32(v1.y * 0.125f);
        }
        const int h = hd >> 6, d = hd & 63;
        const int b = row >> 11, s = row & 2047;
        float* base = Cp + (((size_t)(b * Hn + h) * Sn) * DHn) + d;
        *(float2*)(base + (size_t)s * DHn) = v0;
        *(float2*)(base + (size_t)(s + 8) * DHn) = v1;
      } else {
        *(float2*)&C0[(size_t)row * 1024 + col] = v0;
        *(float2*)&C0[(size_t)(row + 8) * 1024 + col] = v1;
      }
    }
  }
}

// ---------------------------------------------------------------------------
// Causal flash attention, tf32 HMMA, BM=256: 8 warps, each owns TWO 16-row
// blocks (blk=0,1). Block-1 HMMA overlaps block-0 softmax within the warp;
// staging/barrier cost per unit tensor work halves. K/V double-buffered
// cp.async (64-key tiles), P strips warp-private.
// ---------------------------------------------------------------------------
#define ATL 72
#define ASMEM ((4 * 64 * ATL + 256 * ATL) * 4)  // 147456 B

__global__ __launch_bounds__(256) void attn_mma(
    const float* __restrict__ Q, const float* __restrict__ Ka,
    const float* __restrict__ Vt, float* __restrict__ O) {
  extern __shared__ __align__(16) float smd[];
  const int iq = gridDim.x - 1 - blockIdx.x;  // biggest workloads first
  const int bh = blockIdx.y;
  const int bb = bh >> 4, hh = bh & 15;
  const int tid = threadIdx.x;
  const int warp = tid >> 5, lane = tid & 31;
  const int g = lane >> 2, c = lane & 3;
  const int wm = warp * 32;  // 32 q-rows per warp
  const uint32_t sbase = smem_u32(smd);

  const float* Qw = Q + ((size_t)bh * Sn + iq * 256 + wm) * DHn;
  const float* Kb = Ka + (size_t)bh * Sn * DHn;
  const float* Vb = Vt + (size_t)bh * Sn * DHn;  // [dh][S]
  float* Ob = O + ((size_t)bb * Sn + iq * 256 + wm) * Dn + hh * 64;

  // persistent Q fragments, 2 row-blocks
  const uint32_t* Qu = (const uint32_t*)Qw;
  uint32_t aq[2][8][4];
#pragma unroll
  for (int blk = 0; blk < 2; ++blk)
#pragma unroll
    for (int ks = 0; ks < 8; ++ks) {
      const int r0 = blk * 16 + g;
      aq[blk][ks][0] = Qu[r0 * DHn + ks * 8 + c];
      aq[blk][ks][1] = Qu[(r0 + 8) * DHn + ks * 8 + c];
      aq[blk][ks][2] = Qu[r0 * DHn + ks * 8 + c + 4];
      aq[blk][ks][3] = Qu[(r0 + 8) * DHn + ks * 8 + c + 4];
    }

  float oacc[2][8][4];
#pragma unroll
  for (int blk = 0; blk < 2; ++blk)
#pragma unroll
    for (int nt = 0; nt < 8; ++nt)
#pragma unroll
      for (int r = 0; r < 4; ++r) oacc[blk][nt][r] = 0.0f;
  float mrow[2][2], lrow[2][2];
#pragma unroll
  for (int blk = 0; blk < 2; ++blk) {
    mrow[blk][0] = -1e30f; mrow[blk][1] = -1e30f;
    lrow[blk][0] = 0.0f; lrow[blk][1] = 0.0f;
  }

  float* Pw = smd + 4 * 64 * ATL + wm * ATL;  // 32 rows per warp
  const int p0pos = ((c & 1) << 2) | (c >> 1);  // pc(2c): 0,4,1,5

  const int ntiles = 4 * iq + 4;

  {  // prologue: stage tile 0 into buf 0
#pragma unroll
    for (int k = 0; k < 4; ++k) {
      const int idx = tid + k * 256;
      const int r = idx >> 4, c4 = (idx & 15) << 2;
      cpasync16(sbase + (uint32_t)(r * ATL + c4) * 4, Kb + r * 64 + c4);
      cpasync16(sbase + (uint32_t)((2 * 64 * ATL) + r * ATL + c4) * 4,
                Vb + (size_t)r * Sn + c4);
    }
    asm volatile("cp.async.commit_group;" ::: "memory");
  }

  for (int jt = 0; jt < ntiles; ++jt) {
    const int buf = jt & 1;
    if (jt + 1 < ntiles) {
      const int nb = buf ^ 1;
      const float* Kt = Kb + (size_t)(jt + 1) * 64 * DHn;
      const float* Vtt = Vb + (size_t)(jt + 1) * 64;
#pragma unroll
      for (int k = 0; k < 4; ++k) {
        const int idx = tid + k * 256;
        const int r = idx >> 4, c4 = (idx & 15) << 2;
        cpasync16(sbase + (uint32_t)(nb * 64 * ATL + r * ATL + c4) * 4,
                  Kt + r * 64 + c4);
        cpasync16(sbase + (uint32_t)((2 + nb) * 64 * ATL + r * ATL + c4) * 4,
                  Vtt + (size_t)r * Sn + c4);
      }
      asm volatile("cp.async.commit_group;" ::: "memory");
      asm volatile("cp.async.wait_group 1;" ::: "memory");
    } else {
      asm volatile("cp.async.wait_group 0;" ::: "memory");
    }
    __syncthreads();

    const uint32_t* Ku = (const uint32_t*)(smd + buf * 64 * ATL);
    const uint32_t* Vu = (const uint32_t*)(smd + (2 + buf) * 64 * ATL);

    // ---- S + softmax + P store, per row-block ----
#pragma unroll
    for (int blk = 0; blk < 2; ++blk) {
      float sacc[8][4];
#pragma unroll
      for (int nt = 0; nt < 8; ++nt) {
#pragma unroll
        for (int r = 0; r < 4; ++r) sacc[nt][r] = 0.0f;
#pragma unroll
        for (int ks = 0; ks < 8; ++ks) {
          const uint2 b2 =
              *(const uint2*)&Ku[(nt * 8 + g) * ATL + ks * 8 + 2 * c];
          const uint32_t bk[2] = {b2.x, b2.y};
          mma1688(sacc[nt], aq[blk][ks], bk);
        }
      }

      if (jt >= 4 * iq) {  // only the last 4 tiles can clip
        const int row0 = iq * 256 + wm + blk * 16 + g;
#pragma unroll
        for (int nt = 0; nt < 8; ++nt) {
          const int col = jt * 64 + nt * 8 + 2 * c;
          if (col > row0) sacc[nt][0] = -1e30f;
          if (col + 1 > row0) sacc[nt][1] = -1e30f;
          if (col > row0 + 8) sacc[nt][2] = -1e30f;
          if (col + 1 > row0 + 8) sacc[nt][3] = -1e30f;
        }
      }

      float r0 = -1e30f, r1 = -1e30f;
#pragma unroll
      for (int nt = 0; nt < 8; ++nt) {
        r0 = fmaxf(r0, fmaxf(sacc[nt][0], sacc[nt][1]));
        r1 = fmaxf(r1, fmaxf(sacc[nt][2], sacc[nt][3]));
      }
#pragma unroll
      for (int off = 1; off <= 2; off <<= 1) {
        r0 = fmaxf(r0, __shfl_xor_sync(0xffffffffu, r0, off));
        r1 = fmaxf(r1, __shfl_xor_sync(0xffffffffu, r1, off));
      }
      const float mn0 = fmaxf(mrow[blk][0], r0);
      const float mn1 = fmaxf(mrow[blk][1], r1);
      const float al0 = __expf(mrow[blk][0] - mn0);
      const float al1 = __expf(mrow[blk][1] - mn1);
      mrow[blk][0] = mn0; mrow[blk][1] = mn1;

      float* Pb = Pw + blk * 16 * ATL;
      float ps0 = 0.0f, ps1 = 0.0f;
#pragma unroll
      for (int nt = 0; nt < 8; ++nt) {
        const float p0 = __expf(sacc[nt][0] - mn0);
        const float p1 = __expf(sacc[nt][1] - mn0);
        const float p2 = __expf(sacc[nt][2] - mn1);
        const float p3 = __expf(sacc[nt][3] - mn1);
        ps0 += p0 + p1; ps1 += p2 + p3;
        float* pr0 = Pb + g * ATL + nt * 8 + p0pos;
        float* pr1 = Pb + (g + 8) * ATL + nt * 8 + p0pos;
        pr0[0] = to_tf32(p0); pr0[2] = to_tf32(p1);
        pr1[0] = to_tf32(p2); pr1[2] = to_tf32(p3);
      }
#pragma unroll
      for (int off = 1; off <= 2; off <<= 1) {
        ps0 += __shfl_xor_sync(0xffffffffu, ps0, off);
        ps1 += __shfl_xor_sync(0xffffffffu, ps1, off);
      }
      lrow[blk][0] = lrow[blk][0] * al0 + ps0;
      lrow[blk][1] = lrow[blk][1] * al1 + ps1;
#pragma unroll
      for (int nt = 0; nt < 8; ++nt) {
        oacc[blk][nt][0] *= al0; oacc[blk][nt][1] *= al0;
        oacc[blk][nt][2] *= al1; oacc[blk][nt][3] *= al1;
      }
    }
    __syncwarp();  // P strips are warp-private

    // ---- PV, per row-block ----
#pragma unroll
    for (int blk = 0; blk < 2; ++blk) {
      const uint32_t* Pu = (const uint32_t*)(Pw + blk * 16 * ATL);
#pragma unroll
      for (int ks = 0; ks < 8; ++ks) {
        const uint2 a02 = *(const uint2*)&Pu[g * ATL + ks * 8 + 2 * c];
        const uint2 a13 = *(const uint2*)&Pu[(g + 8) * ATL + ks * 8 + 2 * c];
        const uint32_t ap[4] = {a02.x, a13.x, a02.y, a13.y};
#pragma unroll
        for (int nt = 0; nt < 8; ++nt) {
          const uint2 b2 =
              *(const uint2*)&Vu[(nt * 8 + g) * ATL + ks * 8 + 2 * c];
          const uint32_t bv[2] = {b2.x, b2.y};
          mma1688(oacc[blk][nt], ap, bv);
        }
      }
    }
    __syncthreads();  // all reads of buf done before it is restaged
  }

  // epilogue: [B,S,D], tf32-rounded, pc-packed positions (feeds gemm<1>)
#pragma unroll
  for (int blk = 0; blk < 2; ++blk) {
    const float i0 = 1.0f / lrow[blk][0], i1 = 1.0f / lrow[blk][1];
    float* Oblk = Ob + (size_t)(blk * 16) * Dn;
#pragma unroll
    for (int nt = 0; nt < 8; ++nt) {
      const int j = nt * 8 + p0pos;
      Oblk[(size_t)g * Dn + j] = to_tf32(oacc[blk][nt][0] * i0);
      Oblk[(size_t)g * Dn + j + 2] = to_tf32(oacc[blk][nt][1] * i0);
      Oblk[(size_t)(g + 8) * Dn + j] = to_tf32(oacc[blk][nt][2] * i1);
      Oblk[(size_t)(g + 8) * Dn + j + 2] = to_tf32(oacc[blk][nt][3] * i1);
    }
  }
}

extern "C" void kernel_launch(void* const* d_in, const int* in_sizes, int n_in,
                              void* d_out, int out_size) {
  (void)in_sizes; (void)n_in;
  const float* x = (const float*)d_in[0];
  const float* w_in = (const float*)d_in[1];
  const float* b_in = (const float*)d_in[2];
  const float* w_out = (const float*)d_in[3];
  const float* b_out = (const float*)d_in[4];
  float* out = (float*)d_out;

  const size_t leaf = (size_t)Bn * Sn * Dn;
  float *gq = nullptr, *ga = nullptr, *gx = nullptr;
  float *wt1 = nullptr, *wt2 = nullptr, *gka = nullptr, *gvt = nullptr;
  cudaGetSymbolAddress((void**)&gq, g_q);
  cudaGetSymbolAddress((void**)&ga, g_attn);
  cudaGetSymbolAddress((void**)&gx, g_x);
  cudaGetSymbolAddress((void**)&wt1, g_wt1);
  cudaGetSymbolAddress((void**)&wt2, g_wt2);
  cudaGetSymbolAddress((void**)&gka, g_ka);
  cudaGetSymbolAddress((void**)&gvt, g_vt);

  float *k_out, *v_out;
  if ((size_t)out_size >= 3 * leaf) {
    k_out = out + leaf;
    v_out = out + 2 * leaf;
  } else {
    float *gk, *gv;
    cudaGetSymbolAddress((void**)&gk, g_kfall);
    cudaGetSymbolAddress((void**)&gv, g_vfall);
    k_out = gk;
    v_out = gv;
  }

  cudaFuncSetAttribute(gemm_mma<0>, cudaFuncAttributeMaxDynamicSharedMemorySize,
                       GEMM_SMEM);
  cudaFuncSetAttribute(gemm_mma<1>, cudaFuncAttributeMaxDynamicSharedMemorySize,
                       GEMM_SMEM);
  cudaFuncSetAttribute(attn_mma, cudaFuncAttributeMaxDynamicSharedMemorySize,
                       ASMEM);

  // 0) batched prep: pack x, transpose+pack both weights (one launch)
  prep_pre<<<12288, 256>>>(x, gx, w_in, wt1, w_out, wt2);

  // 1) QKV projection; Q scaled+rounded into g_q, exact k/v to outputs
  gemm_mma<0><<<dim3(24, 64), 128, GEMM_SMEM>>>(gx, wt1, b_in, gq, k_out,
                                                v_out);

  // 2) batched attention operand prep: pack K, transpose+pack V (one launch)
  prep_post<<<16384, 256>>>(k_out, gka, v_out, gvt);

  // 3) causal flash attention (BM=256) -> [B,S,D] rounded+packed
  attn_mma<<<dim3(8, 64), 256, ASMEM>>>(gq, gka, gvt, ga);

  // 4) output projection (plain row-major A)
  gemm_mma<1><<<dim3(8, 64), 128, GEMM_SMEM>>>(ga, wt2, b_out, out, nullptr,
                                               nullptr);
}

// round 17
// speedup vs baseline: 1.0627x; 1.0627x over previous
#include <cuda_runtime.h>
#include <math.h>
#include <cstdint>

#define Bn 4
#define Sn 2048
#define Dn 1024
#define Hn 16
#define DHn 64
#define KDIM 1024

// ---------------- scratch (__device__ globals; no allocs allowed) ----------
__device__ float g_q[(size_t)Bn * Hn * Sn * DHn];     // Q [B,H,S,dh] scaled+tf32
__device__ float g_attn[(size_t)Bn * Sn * Dn];        // attn out [B,S,D] tf32+packed
__device__ float g_x[(size_t)Bn * Sn * Dn];           // x tf32+packed
__device__ float g_kfall[(size_t)Bn * Hn * Sn * DHn];
__device__ float g_vfall[(size_t)Bn * Hn * Sn * DHn];
__device__ float g_ka[(size_t)Bn * Hn * Sn * DHn];    // K tf32, dh-cols packed
__device__ float g_vt[(size_t)Bn * Hn * Sn * DHn];    // V^T [B,H,dh,S] tf32, packed
__device__ float g_wt1[(size_t)3072 * 1024];          // W_in^T  tf32+packed
__device__ float g_wt2[(size_t)1024 * 1024];          // W_out^T tf32+packed

__device__ __forceinline__ float to_tf32(float x) {
  float y;
  asm("cvt.rna.tf32.f32 %0, %1;" : "=f"(y) : "f"(x));
  return y;
}

__device__ __forceinline__ void mma1688(float* c, const uint32_t* a,
                                        const uint32_t* b) {
  asm volatile(
      "mma.sync.aligned.m16n8k8.row.col.f32.tf32.tf32.f32 "
      "{%0,%1,%2,%3}, {%4,%5,%6,%7}, {%8,%9}, {%0,%1,%2,%3};"
      : "+f"(c[0]), "+f"(c[1]), "+f"(c[2]), "+f"(c[3])
      : "r"(a[0]), "r"(a[1]), "r"(a[2]), "r"(a[3]), "r"(b[0]), "r"(b[1]));
}

__device__ __forceinline__ uint32_t smem_u32(const void* p) {
  uint32_t a;
  asm("{ .reg .u64 t; cvta.to.shared.u64 t, %1; cvt.u32.u64 %0, t; }"
      : "=r"(a) : "l"(p));
  return a;
}

__device__ __forceinline__ void cpasync16(uint32_t dst, const void* src) {
  asm volatile("cp.async.cg.shared.global [%0], [%1], 16;" ::"r"(dst),
               "l"(src) : "memory");
}

// ---------------------------------------------------------------------------
// device helpers for batched prep
// ---------------------------------------------------------------------------
__device__ __forceinline__ void wtrans_tile(const float* __restrict__ W,
                                            float* __restrict__ WT, int K,
                                            int N, int n0, int k0,
                                            float (*t)[33]) {
  const int tx = threadIdx.x & 31, ty = threadIdx.x >> 5;
#pragma unroll
  for (int i = 0; i < 4; ++i)
    t[ty + i * 8][tx] = W[(size_t)(k0 + ty + i * 8) * N + n0 + tx];
  __syncthreads();
  const int kp = (tx & ~7) | (2 * (tx & 3) + ((tx >> 2) & 1));
#pragma unroll
  for (int i = 0; i < 4; ++i)
    WT[(size_t)(n0 + ty + i * 8) * K + k0 + kp] = to_tf32(t[tx][ty + i * 8]);
}

__device__ __forceinline__ void packrow_quad(const float* __restrict__ S,
                                             float* __restrict__ D,
                                             size_t blk) {
  const size_t i = (blk * 256 + threadIdx.x) * 4;
  float4 v = *(const float4*)(S + i);
  const int off = (i & 4) ? 1 : 0;
  float* dst = D + (i & ~(size_t)7) + off;
  dst[0] = to_tf32(v.x);
  dst[2] = to_tf32(v.y);
  dst[4] = to_tf32(v.z);
  dst[6] = to_tf32(v.w);
}

// prep_pre: blocks [0,8192) pack x; [8192,11264) wtrans W_in; [11264,12288) W_out
__global__ __launch_bounds__(256) void prep_pre(
    const float* __restrict__ x, float* __restrict__ gx,
    const float* __restrict__ w_in, float* __restrict__ wt1,
    const float* __restrict__ w_out, float* __restrict__ wt2) {
  __shared__ float t[32][33];
  const int b = blockIdx.x;
  if (b < 8192) {
    packrow_quad(x, gx, (size_t)b);
  } else if (b < 11264) {
    const int idx = b - 8192;
    wtrans_tile(w_in, wt1, 1024, 3072, (idx % 96) * 32, (idx / 96) * 32, t);
  } else {
    const int idx = b - 11264;
    wtrans_tile(w_out, wt2, 1024, 1024, (idx % 32) * 32, (idx / 32) * 32, t);
  }
}

// prep_post: blocks [0,8192) pack K; [8192,16384) transpose+pack V
__global__ __launch_bounds__(256) void prep_post(
    const float* __restrict__ K, float* __restrict__ Ka,
    const float* __restrict__ V, float* __restrict__ VT) {
  __shared__ float t[32][33];
  const int b = blockIdx.x;
  if (b < 8192) {
    packrow_quad(K, Ka, (size_t)b);
  } else {
    const int idx = b - 8192;
    const int s0 = (idx & 63) * 32, d0 = ((idx >> 6) & 1) * 32, bh = idx >> 7;
    const float* Vb = V + (size_t)bh * Sn * DHn;
    float* Tb = VT + (size_t)bh * Sn * DHn;
    const int tx = threadIdx.x & 31, ty = threadIdx.x >> 5;
#pragma unroll
    for (int i = 0; i < 4; ++i)
      t[ty + i * 8][tx] =
          to_tf32(Vb[(size_t)(s0 + ty + i * 8) * DHn + d0 + tx]);
    __syncthreads();
    const int sx = (tx & ~7) | (2 * (tx & 3) + ((tx >> 2) & 1));
#pragma unroll
    for (int i = 0; i < 4; ++i)
      Tb[(size_t)(d0 + ty + i * 8) * Sn + s0 + sx] = t[tx][ty + i * 8];
  }
}

// ---------------------------------------------------------------------------
// tf32 HMMA GEMM (validated R12). 4 warps, CTA 128x128, warp 64x64, KC=32,
// 3-stage cp.async, 8-float-group XOR swizzle (conflict-free float2 loads).
// ---------------------------------------------------------------------------
#define KC 32
#define TILE_F (128 * 32)
#define STAGE_F (2 * TILE_F)
#define NSTAGE 3
#define GEMM_SMEM (NSTAGE * STAGE_F * 4)  // 98304 B

template <int MODE>
__global__ __launch_bounds__(128) void gemm_mma(
    const float* __restrict__ A, const float* __restrict__ Bt,
    const float* __restrict__ bias, float* __restrict__ C0,
    float* __restrict__ Ck, float* __restrict__ Cv) {
  extern __shared__ __align__(16) float sm[];
  const uint32_t sbase = smem_u32(sm);
  const int tid = threadIdx.x;
  const int m0 = blockIdx.y * 128, n0 = blockIdx.x * 128;
  const int warp = tid >> 5, lane = tid & 31;
  const int g = lane >> 2, c = lane & 3;
  const int wm = (warp & 1) * 64, wn = (warp >> 1) * 64;

  const float* Ab = A + (size_t)m0 * KDIM;
  const float* Bb = Bt + (size_t)n0 * KDIM;

  float acc[4][8][4];
#pragma unroll
  for (int mt = 0; mt < 4; ++mt)
#pragma unroll
    for (int nt = 0; nt < 8; ++nt)
#pragma unroll
      for (int r = 0; r < 4; ++r) acc[mt][nt][r] = 0.0f;

  const int NCH = KDIM / KC;

  auto issue = [&](int ch, int st) {
    const uint32_t As = sbase + (uint32_t)(st * STAGE_F) * 4;
    const uint32_t Bs = As + (uint32_t)TILE_F * 4;
    const int ko = ch * KC;
#pragma unroll
    for (int i = 0; i < 8; ++i) {
      const int idx = i * 128 + tid;
      const int r = idx >> 3, qi = idx & 7;
      const int gi = qi >> 1;
      const uint32_t dcol =
          (uint32_t)((((gi ^ (r & 3)) << 3) + ((qi & 1) << 2)));
      cpasync16(As + (uint32_t)(r * 32 + dcol) * 4,
                Ab + (size_t)r * KDIM + ko + qi * 4);
      cpasync16(Bs + (uint32_t)(r * 32 + dcol) * 4,
                Bb + (size_t)r * KDIM + ko + qi * 4);
    }
    asm volatile("cp.async.commit_group;" ::: "memory");
  };

  issue(0, 0);
  issue(1, 1);

  for (int ch = 0; ch < NCH; ++ch) {
    const int st = ch % NSTAGE;
    if (ch + 1 < NCH)
      asm volatile("cp.async.wait_group 1;" ::: "memory");
    else
      asm volatile("cp.async.wait_group 0;" ::: "memory");
    __syncthreads();
    if (ch + 2 < NCH) issue(ch + 2, (ch + 2) % NSTAGE);

    const uint32_t* Au = (const uint32_t*)(sm + st * STAGE_F);
    const uint32_t* Bu = Au + TILE_F;
#pragma unroll
    for (int ks = 0; ks < KC / 8; ++ks) {
      const int fcol = (((ks ^ (g & 3)) << 3) + 2 * c);
      uint32_t af[4][4], bf[8][2];
#pragma unroll
      for (int mt = 0; mt < 4; ++mt) {
        const int row = wm + mt * 16 + g;
        const uint2 lo = *(const uint2*)&Au[(row << 5) + fcol];
        const uint2 hi = *(const uint2*)&Au[((row + 8) << 5) + fcol];
        af[mt][0] = lo.x; af[mt][1] = hi.x;
        af[mt][2] = lo.y; af[mt][3] = hi.y;
      }
#pragma unroll
      for (int nt = 0; nt < 8; ++nt) {
        const uint2 b2 = *(const uint2*)&Bu[((wn + nt * 8 + g) << 5) + fcol];
        bf[nt][0] = b2.x; bf[nt][1] = b2.y;
      }
#pragma unroll
      for (int mt = 0; mt < 4; ++mt)
#pragma unroll
        for (int nt = 0; nt < 8; ++nt) mma1688(acc[mt][nt], af[mt], bf[nt]);
    }
  }

#pragma unroll
  for (int mt = 0; mt < 4; ++mt) {
#pragma unroll
    for (int nt = 0; nt < 8; ++nt) {
      const int row = m0 + wm + mt * 16 + g;
      const int col = n0 + wn + nt * 8 + 2 * c;
      const float b0 = bias[col], b1 = bias[col + 1];
      float2 v0 = {acc[mt][nt][0] + b0, acc[mt][nt][1] + b1};
      float2 v1 = {acc[mt][nt][2] + b0, acc[mt][nt][3] + b1};
      if (MODE == 0) {
        const int which = col >> 10, hd = col & 1023;
        float* Cp = (which == 0) ? C0 : ((which == 1) ? Ck : Cv);
        if (which == 0) {
          v0.x = to_tf32(v0.x * 0.125f); v0.y = to_tf32(v0.y * 0.125f);
          v1.x = to_tf32(v1.x * 0.125f); v1.y = to_tf32(v1.y * 0.125f);
        }
        const int h = hd >> 6, d = hd & 63;
        const int b = row >> 11, s = row & 2047;
        float* base = Cp + (((size_t)(b * Hn + h) * Sn) * DHn) + d;
        *(float2*)(base + (size_t)s * DHn) = v0;
        *(float2*)(base + (size_t)(s + 8) * DHn) = v1;
      } else {
        *(float2*)&C0[(size_t)row * 1024 + col] = v0;
        *(float2*)&C0[(size_t)(row + 8) * 1024 + col] = v1;
      }
    }
  }
}

// ---------------------------------------------------------------------------
// Causal flash attention, tf32 HMMA (exact R12 version: BM=128, 8 warps,
// 16 q-rows/warp, regs ~166, 2 CTAs/SM-limited-by-smem). cp.async double
// buffering, warp-private P strips, packed float2 fragment loads @ ATL=72.
// Output written to [B,S,D], tf32-rounded, pc-packed (feeds gemm<1>).
// ---------------------------------------------------------------------------
#define ATL 72
#define ASMEM ((4 * 64 * ATL + 128 * ATL) * 4)  // 110592 B

__global__ __launch_bounds__(256) void attn_mma(
    const float* __restrict__ Q, const float* __restrict__ Ka,
    const float* __restrict__ Vt, float* __restrict__ O) {
  extern __shared__ __align__(16) float smd[];
  const int iq = gridDim.x - 1 - blockIdx.x;  // biggest workloads first
  const int bh = blockIdx.y;
  const int b = bh >> 4, h = bh & 15;
  const int tid = threadIdx.x;
  const int warp = tid >> 5, lane = tid & 31;
  const int g = lane >> 2, c = lane & 3;
  const int wm = warp * 16;
  const uint32_t sbase = smem_u32(smd);

  const float* Qw = Q + ((size_t)bh * Sn + iq * 128 + wm) * DHn;
  const float* Kb = Ka + (size_t)bh * Sn * DHn;
  const float* Vb = Vt + (size_t)bh * Sn * DHn;  // [dh][S]
  float* Ob = O + ((size_t)b * Sn + iq * 128 + wm) * Dn + h * 64;

  const uint32_t* Qu = (const uint32_t*)Qw;
  uint32_t aq[8][4];
#pragma unroll
  for (int ks = 0; ks < 8; ++ks) {
    aq[ks][0] = Qu[g * DHn + ks * 8 + c];
    aq[ks][1] = Qu[(g + 8) * DHn + ks * 8 + c];
    aq[ks][2] = Qu[g * DHn + ks * 8 + c + 4];
    aq[ks][3] = Qu[(g + 8) * DHn + ks * 8 + c + 4];
  }

  float oacc[8][4];
#pragma unroll
  for (int nt = 0; nt < 8; ++nt)
#pragma unroll
    for (int r = 0; r < 4; ++r) oacc[nt][r] = 0.0f;
  float m0 = -1e30f, m1 = -1e30f, l0 = 0.0f, l1 = 0.0f;

  float* Pw = smd + 4 * 64 * ATL + wm * ATL;
  const uint32_t* Pu = (const uint32_t*)Pw;
  const int p0pos = ((c & 1) << 2) | (c >> 1);  // pc(2c): 0,4,1,5

  const int ntiles = 2 * iq + 2;

  {
#pragma unroll
    for (int k = 0; k < 4; ++k) {
      const int idx = tid + k * 256;
      const int r = idx >> 4, c4 = (idx & 15) << 2;
      cpasync16(sbase + (uint32_t)(r * ATL + c4) * 4, Kb + r * 64 + c4);
      cpasync16(sbase + (uint32_t)((2 * 64 * ATL) + r * ATL + c4) * 4,
                Vb + (size_t)r * Sn + c4);
    }
    asm volatile("cp.async.commit_group;" ::: "memory");
  }

  for (int jt = 0; jt < ntiles; ++jt) {
    const int buf = jt & 1;
    if (jt + 1 < ntiles) {
      const int nb = buf ^ 1;
      const float* Kt = Kb + (size_t)(jt + 1) * 64 * DHn;
      const float* Vtt = Vb + (size_t)(jt + 1) * 64;
#pragma unroll
      for (int k = 0; k < 4; ++k) {
        const int idx = tid + k * 256;
        const int r = idx >> 4, c4 = (idx & 15) << 2;
        cpasync16(sbase + (uint32_t)(nb * 64 * ATL + r * ATL + c4) * 4,
                  Kt + r * 64 + c4);
        cpasync16(sbase + (uint32_t)((2 + nb) * 64 * ATL + r * ATL + c4) * 4,
                  Vtt + (size_t)r * Sn + c4);
      }
      asm volatile("cp.async.commit_group;" ::: "memory");
      asm volatile("cp.async.wait_group 1;" ::: "memory");
    } else {
      asm volatile("cp.async.wait_group 0;" ::: "memory");
    }
    __syncthreads();

    const uint32_t* Ku = (const uint32_t*)(smd + buf * 64 * ATL);
    const uint32_t* Vu = (const uint32_t*)(smd + (2 + buf) * 64 * ATL);

    float sacc[8][4];
#pragma unroll
    for (int nt = 0; nt < 8; ++nt) {
#pragma unroll
      for (int r = 0; r < 4; ++r) sacc[nt][r] = 0.0f;
#pragma unroll
      for (int ks = 0; ks < 8; ++ks) {
        const uint2 b2 = *(const uint2*)&Ku[(nt * 8 + g) * ATL + ks * 8 + 2 * c];
        const uint32_t bk[2] = {b2.x, b2.y};
        mma1688(sacc[nt], aq[ks], bk);
      }
    }

    if (jt >= 2 * iq) {
      const int row0 = iq * 128 + wm + g;
#pragma unroll
      for (int nt = 0; nt < 8; ++nt) {
        const int col = jt * 64 + nt * 8 + 2 * c;
        if (col > row0) sacc[nt][0] = -1e30f;
        if (col + 1 > row0) sacc[nt][1] = -1e30f;
        if (col > row0 + 8) sacc[nt][2] = -1e30f;
        if (col + 1 > row0 + 8) sacc[nt][3] = -1e30f;
      }
    }

    float r0 = -1e30f, r1 = -1e30f;
#pragma unroll
    for (int nt = 0; nt < 8; ++nt) {
      r0 = fmaxf(r0, fmaxf(sacc[nt][0], sacc[nt][1]));
      r1 = fmaxf(r1, fmaxf(sacc[nt][2], sacc[nt][3]));
    }
#pragma unroll
    for (int off = 1; off <= 2; off <<= 1) {
      r0 = fmaxf(r0, __shfl_xor_sync(0xffffffffu, r0, off));
      r1 = fmaxf(r1, __shfl_xor_sync(0xffffffffu, r1, off));
    }
    const float mn0 = fmaxf(m0, r0), mn1 = fmaxf(m1, r1);
    const float al0 = __expf(m0 - mn0), al1 = __expf(m1 - mn1);
    m0 = mn0; m1 = mn1;

    float ps0 = 0.0f, ps1 = 0.0f;
#pragma unroll
    for (int nt = 0; nt < 8; ++nt) {
      const float p0 = __expf(sacc[nt][0] - m0);
      const float p1 = __expf(sacc[nt][1] - m0);
      const float p2 = __expf(sacc[nt][2] - m1);
      const float p3 = __expf(sacc[nt][3] - m1);
      ps0 += p0 + p1; ps1 += p2 + p3;
      float* pr0 = Pw + g * ATL + nt * 8 + p0pos;
      float* pr1 = Pw + (g + 8) * ATL + nt * 8 + p0pos;
      pr0[0] = to_tf32(p0); pr0[2] = to_tf32(p1);
      pr1[0] = to_tf32(p2); pr1[2] = to_tf32(p3);
    }
#pragma unroll
    for (int off = 1; off <= 2; off <<= 1) {
      ps0 += __shfl_xor_sync(0xffffffffu, ps0, off);
      ps1 += __shfl_xor_sync(0xffffffffu, ps1, off);
    }
    l0 = l0 * al0 + ps0;
    l1 = l1 * al1 + ps1;
#pragma unroll
    for (int nt = 0; nt < 8; ++nt) {
      oacc[nt][0] *= al0; oacc[nt][1] *= al0;
      oacc[nt][2] *= al1; oacc[nt][3] *= al1;
    }
    __syncwarp();

#pragma unroll
    for (int ks = 0; ks < 8; ++ks) {
      const uint2 a02 = *(const uint2*)&Pu[g * ATL + ks * 8 + 2 * c];
      const uint2 a13 = *(const uint2*)&Pu[(g + 8) * ATL + ks * 8 + 2 * c];
      const uint32_t ap[4] = {a02.x, a13.x, a02.y, a13.y};
#pragma unroll
      for (int nt = 0; nt < 8; ++nt) {
        const uint2 b2 = *(const uint2*)&Vu[(nt * 8 + g) * ATL + ks * 8 + 2 * c];
        const uint32_t bv[2] = {b2.x, b2.y};
        mma1688(oacc[nt], ap, bv);
      }
    }
    __syncthreads();
  }

  const float i0 = 1.0f / l0, i1 = 1.0f / l1;
#pragma unroll
  for (int nt = 0; nt < 8; ++nt) {
    const int j = nt * 8 + p0pos;
    Ob[(size_t)g * Dn + j] = to_tf32(oacc[nt][0] * i0);
    Ob[(size_t)g * Dn + j + 2] = to_tf32(oacc[nt][1] * i0);
    Ob[(size_t)(g + 8) * Dn + j] = to_tf32(oacc[nt][2] * i1);
    Ob[(size_t)(g + 8) * Dn + j + 2] = to_tf32(oacc[nt][3] * i1);
  }
}

extern "C" void kernel_launch(void* const* d_in, const int* in_sizes, int n_in,
                              void* d_out, int out_size) {
  (void)in_sizes; (void)n_in;
  const float* x = (const float*)d_in[0];
  const float* w_in = (const float*)d_in[1];
  const float* b_in = (const float*)d_in[2];
  const float* w_out = (const float*)d_in[3];
  const float* b_out = (const float*)d_in[4];
  float* out = (float*)d_out;

  const size_t leaf = (size_t)Bn * Sn * Dn;
  float *gq = nullptr, *ga = nullptr, *gx = nullptr;
  float *wt1 = nullptr, *wt2 = nullptr, *gka = nullptr, *gvt = nullptr;
  cudaGetSymbolAddress((void**)&gq, g_q);
  cudaGetSymbolAddress((void**)&ga, g_attn);
  cudaGetSymbolAddress((void**)&gx, g_x);
  cudaGetSymbolAddress((void**)&wt1, g_wt1);
  cudaGetSymbolAddress((void**)&wt2, g_wt2);
  cudaGetSymbolAddress((void**)&gka, g_ka);
  cudaGetSymbolAddress((void**)&gvt, g_vt);

  float *k_out, *v_out;
  if ((size_t)out_size >= 3 * leaf) {
    k_out = out + leaf;
    v_out = out + 2 * leaf;
  } else {
    float *gk, *gv;
    cudaGetSymbolAddress((void**)&gk, g_kfall);
    cudaGetSymbolAddress((void**)&gv, g_vfall);
    k_out = gk;
    v_out = gv;
  }

  cudaFuncSetAttribute(gemm_mma<0>, cudaFuncAttributeMaxDynamicSharedMemorySize,
                       GEMM_SMEM);
  cudaFuncSetAttribute(gemm_mma<1>, cudaFuncAttributeMaxDynamicSharedMemorySize,
                       GEMM_SMEM);
  cudaFuncSetAttribute(attn_mma, cudaFuncAttributeMaxDynamicSharedMemorySize,
                       ASMEM);

  // 0) batched prep: pack x, transpose+pack both weights (one launch)
  prep_pre<<<12288, 256>>>(x, gx, w_in, wt1, w_out, wt2);

  // 1) QKV projection; Q scaled+rounded into g_q, exact k/v to outputs
  gemm_mma<0><<<dim3(24, 64), 128, GEMM_SMEM>>>(gx, wt1, b_in, gq, k_out,
                                                v_out);

  // 2) batched attention operand prep: pack K, transpose+pack V (one launch)
  prep_post<<<16384, 256>>>(k_out, gka, v_out, gvt);

  // 3) causal flash attention (BM=128, R12-validated) -> [B,S,D] packed
  attn_mma<<<dim3(16, 64), 256, ASMEM>>>(gq, gka, gvt, ga);

  // 4) output projection (plain row-major A)
  gemm_mma<1><<<dim3(8, 64), 128, GEMM_SMEM>>>(ga, wt2, b_out, out, nullptr,
                                               nullptr);
}